// round 3
// baseline (speedup 1.0000x reference)
#include <cuda_runtime.h>
#include <cuda_bf16.h>
#include <stdint.h>

// Scatter-add F_st[e] * edge_vec[e] into out[edge_idx[e]], n_atoms x 3.
// g_acc is a 16B-padded accumulator so each edge issues ONE red.global.add.v4.f32.
// The copy kernel both compacts [n,4]->[n,3] into d_out AND resets g_acc to zero,
// maintaining the "g_acc is zero on entry" invariant (device globals are
// zero-initialized at load) -> no separate zeroing launch.

#define MAX_ATOMS 100000

__device__ float4 g_acc[MAX_ATOMS];

__device__ __forceinline__ void red_add_v4(float4* p, float x, float y, float z) {
    asm volatile("red.global.add.v4.f32 [%0], {%1, %2, %3, %4};"
                 :: "l"(p), "f"(x), "f"(y), "f"(z), "f"(0.0f)
                 : "memory");
}

// 256 threads = 8 warps per block; each warp handles 128 consecutive edges.
// edge_vec is loaded warp-coalesced (3x LDG.128 per lane, unit stride across the
// warp) into smem, then re-read per-thread. The 48B-stride LDS.128 pattern is
// bank-conflict-free (each 8-lane phase covers all 32 banks disjointly).
__global__ __launch_bounds__(256)
void scatter_kernel(const float4* __restrict__ F4,
                    const float4* __restrict__ V4,
                    const int4*   __restrict__ I4,
                    int n_full_warps, int n_edges, int n_atoms) {
    __shared__ float4 sv[8][96];

    int gwarp = (blockIdx.x * blockDim.x + threadIdx.x) >> 5;
    int lane  = threadIdx.x & 31;
    int w     = threadIdx.x >> 5;

    if (gwarp < n_full_warps) {
        // Stage this warp's 96 float4 of edge_vec, coalesced.
        const float4* vbase = V4 + (size_t)gwarp * 96;
        sv[w][lane]      = vbase[lane];
        sv[w][lane + 32] = vbase[lane + 32];
        sv[w][lane + 64] = vbase[lane + 64];

        int t = gwarp * 32 + lane;       // quad-of-edges index
        float4 f  = F4[t];
        int4   id = I4[t];
        __syncwarp();

        float4 a = sv[w][3 * lane + 0];
        float4 b = sv[w][3 * lane + 1];
        float4 c = sv[w][3 * lane + 2];

        // edge layout: e0=(a.x,a.y,a.z) e1=(a.w,b.x,b.y) e2=(b.z,b.w,c.x) e3=(c.y,c.z,c.w)
        if ((unsigned)id.x < (unsigned)n_atoms)
            red_add_v4(&g_acc[id.x], f.x * a.x, f.x * a.y, f.x * a.z);
        if ((unsigned)id.y < (unsigned)n_atoms)
            red_add_v4(&g_acc[id.y], f.y * a.w, f.y * b.x, f.y * b.y);
        if ((unsigned)id.z < (unsigned)n_atoms)
            red_add_v4(&g_acc[id.z], f.z * b.z, f.z * b.w, f.z * c.x);
        if ((unsigned)id.w < (unsigned)n_atoms)
            red_add_v4(&g_acc[id.w], f.w * c.y, f.w * c.z, f.w * c.w);
    } else if (gwarp == n_full_warps && lane == 0) {
        // scalar tail (n_edges % 128 edges), one thread
        const float* F   = (const float*)F4;
        const float* V   = (const float*)V4;
        const int*   IDX = (const int*)I4;
        for (int e = n_full_warps * 128; e < n_edges; e++) {
            float fe = F[e];
            int   i  = IDX[e];
            if ((unsigned)i < (unsigned)n_atoms)
                red_add_v4(&g_acc[i], fe * V[3 * e + 0], fe * V[3 * e + 1], fe * V[3 * e + 2]);
        }
    }
}

// Compact [n,4] -> [n,3] into d_out AND reset the accumulator for the next call.
__global__ __launch_bounds__(256)
void copy_zero_kernel(float* __restrict__ out, int n_atoms) {
    int i = blockIdx.x * blockDim.x + threadIdx.x;
    if (i < n_atoms) {
        float4 v = g_acc[i];
        g_acc[i] = make_float4(0.f, 0.f, 0.f, 0.f);
        out[3 * i + 0] = v.x;
        out[3 * i + 1] = v.y;
        out[3 * i + 2] = v.z;
    }
}

extern "C" void kernel_launch(void* const* d_in, const int* in_sizes, int n_in,
                              void* d_out, int out_size) {
    const float4* F4 = (const float4*)d_in[0];   // F_st     [E,1] f32
    const float4* V4 = (const float4*)d_in[1];   // edge_vec [E,3] f32
    const int4*   I4 = (const int4*)d_in[2];     // edge_idx [E]   i32
    float* out = (float*)d_out;                  // [n_atoms,3] f32

    int n_edges = in_sizes[0];
    int n_atoms = out_size / 3;
    if (n_atoms > MAX_ATOMS) n_atoms = MAX_ATOMS;

    int n_full_warps = n_edges / 128;            // 128 edges per warp
    int n_warps      = n_full_warps + 1;         // +1 warp for scalar tail
    int threads      = n_warps * 32;

    const int TB = 256;
    scatter_kernel<<<(threads + TB - 1) / TB, TB>>>(F4, V4, I4,
                                                    n_full_warps, n_edges, n_atoms);
    copy_zero_kernel<<<(n_atoms + TB - 1) / TB, TB>>>(out, n_atoms);
}